// round 17
// baseline (speedup 1.0000x reference)
#include <cuda_runtime.h>
#include <cuda_bf16.h>
#include <cstdint>

// 4096-pt FWHT, 8192 rows fp32.  Final consolidated champion.
// One 64-thread CTA, RPC=2 rows (grid 4096), double-buffered cp.async.cg:
//   prologue stages BOTH rows (two commit groups) | iter k: wait -> bar ->
//   round A -> bar -> round B (scale folded into last stage) -> STG.128.
// Radix 64x64: Round A butterflies element bits [7:2], Round B bits
// {[11:8],[1:0]}. Additive skew phys(e) = e + (e>>8)*4 -> all smem access
// patterns bank-conflict-free, folds to LDS immediates. fma.rn.f32x2 math.
// Each buffer is written exactly once per CTA -> no trailing WAR barrier.

#define ROW    4096
#define TPR    64
#define SROW   4156          // skewed row words, exact (16B-aligned: 4156*4=16624)
#define RPC    2

__device__ __forceinline__ float2 ffma2(float2 b, float2 m, float2 a) {
    float2 r;
    asm("fma.rn.f32x2 %0, %1, %2, %3;"
        : "=l"(reinterpret_cast<unsigned long long&>(r))
        : "l"(reinterpret_cast<const unsigned long long&>(b)),
          "l"(reinterpret_cast<const unsigned long long&>(m)),
          "l"(reinterpret_cast<const unsigned long long&>(a)));
    return r;
}

__device__ __forceinline__ float2 fmul2(float2 a, float2 m) {
    float2 r;
    asm("mul.rn.f32x2 %0, %1, %2;"
        : "=l"(reinterpret_cast<unsigned long long&>(r))
        : "l"(reinterpret_cast<const unsigned long long&>(a)),
          "l"(reinterpret_cast<const unsigned long long&>(m)));
    return r;
}

// 64-pt FWHT over 32 packed float2, WITHOUT the last (h=16) packed stage.
__device__ __forceinline__ void fwht64p_nolast(float2* v) {
    const float2 P1 = make_float2(1.0f, 1.0f);
    const float2 M1 = make_float2(-1.0f, -1.0f);
#pragma unroll
    for (int p = 0; p < 32; p++) {           // h=1 (intra-pair)
        float lo = v[p].x, hi = v[p].y;
        v[p].x = lo + hi;
        v[p].y = lo - hi;
    }
#pragma unroll
    for (int h = 1; h < 16; h <<= 1) {       // h=2..32 packed
#pragma unroll
        for (int p = 0; p < 32; p++) {
            if ((p & h) == 0) {
                float2 a = v[p], b = v[p + h];
                v[p]     = ffma2(b, P1, a);
                v[p + h] = ffma2(b, M1, a);
            }
        }
    }
}

// Full 64-pt FWHT (for round A).
__device__ __forceinline__ void fwht64p(float2* v) {
    const float2 P1 = make_float2(1.0f, 1.0f);
    const float2 M1 = make_float2(-1.0f, -1.0f);
    fwht64p_nolast(v);
#pragma unroll
    for (int p = 0; p < 16; p++) {           // h=16 (last stage)
        float2 a = v[p], b = v[p + 16];
        v[p]      = ffma2(b, P1, a);
        v[p + 16] = ffma2(b, M1, a);
    }
}

__device__ __forceinline__ void cp_async16(uint32_t dst_smem, const void* src) {
    asm volatile("cp.async.cg.shared.global [%0], [%1], 16;"
                 :: "r"(dst_smem), "l"(src) : "memory");
}
__device__ __forceinline__ void cp_commit() {
    asm volatile("cp.async.commit_group;" ::: "memory");
}
template <int N>
__device__ __forceinline__ void cp_wait() {
    asm volatile("cp.async.wait_group %0;" :: "n"(N) : "memory");
}

// Stage one row into a smem buffer: float4 q = i*64 + t (coalesced),
// element e = 256*i + 4*t -> skewed word 260*i + 4*t (16B aligned).
__device__ __forceinline__ void stage_row(uint32_t sbuf, const float4* x4, int t) {
#pragma unroll
    for (int i = 0; i < 16; i++)
        cp_async16(sbuf + (260u * i + 4u * t) * 4u, x4 + i * 64 + t);
    cp_commit();
}

template <int RPC_T>
__global__ void __launch_bounds__(TPR)
fwht4096_kernel(const float* __restrict__ in, float* __restrict__ out) {
    static_assert(RPC_T <= 2, "no-trailing-barrier scheme requires RPC_T <= 2");
    __shared__ __align__(16) float s[2 * SROW];

    const int t = threadIdx.x;
    const long row0 = (long)blockIdx.x * RPC_T;

    uint32_t sbase;
    asm("{ .reg .u64 tmp; cvta.to.shared.u64 tmp, %1; cvt.u32.u64 %0, tmp; }"
        : "=r"(sbase) : "l"(s));

    // Prologue: stage BOTH rows up-front, separate commit groups, in order.
    stage_row(sbase, reinterpret_cast<const float4*>(in + row0 * ROW), t);
    if (RPC_T > 1)
        stage_row(sbase + SROW * 4u,
                  reinterpret_cast<const float4*>(in + (row0 + 1) * ROW), t);

    const int j = t >> 2, r = t & 3;   // round-A ownership

#pragma unroll
    for (int k = 0; k < RPC_T; k++) {
        // Wait until row k's group is complete (newer groups may stay pending).
        if (k == 0 && RPC_T > 1) cp_wait<1>();
        else                     cp_wait<0>();
        __syncthreads();    // cross-thread visibility of row k's cp.async data

        float* sm = s + (k & 1) * SROW;

        // ---- Round A: thread (j,r) owns e = j*256 + m*4 + r, m = 0..63.
        // Skewed word = 260*j + 4*m + r; banks (4j+r) mod 32 per phase -> clean.
        {
            float* base = sm + 260 * j + r;
            float2 v[32];
#pragma unroll
            for (int p = 0; p < 32; p++)
                v[p] = make_float2(base[8 * p], base[8 * p + 4]);
            fwht64p(v);   // butterflies bits [7:2]
#pragma unroll
            for (int p = 0; p < 32; p++) {
                base[8 * p]     = v[p].x;
                base[8 * p + 4] = v[p].y;
            }
        }
        __syncthreads();   // round A scatter -> round B gather

        // ---- Round B: thread t owns e = jj*256 + 4*t + rr (LDS.128 gather),
        // butterflies bits {[11:8],[1:0]}; the 1/64 scale is folded into the
        // final (h=16) butterfly stage: (a±b)*s = ffma2(b, ±S, a*S).
        {
            float2 w[32];
#pragma unroll
            for (int jj = 0; jj < 16; jj++) {
                float4 q = *reinterpret_cast<const float4*>(sm + 260 * jj + 4 * t);
                w[2 * jj]     = make_float2(q.x, q.y);
                w[2 * jj + 1] = make_float2(q.z, q.w);
            }
            fwht64p_nolast(w);   // stages h=1..32

            const float2 SP = make_float2( 1.0f / 64.0f,  1.0f / 64.0f);
            const float2 SM = make_float2(-1.0f / 64.0f, -1.0f / 64.0f);
            float4* y4 = reinterpret_cast<float4*>(out + (row0 + k) * ROW);
            // Last stage pairs (p, p+16) = float4 lanes of jj and jj+8.
#pragma unroll
            for (int jj = 0; jj < 8; jj++) {
#pragma unroll
                for (int half = 0; half < 2; half++) {
                    const int p = 2 * jj + half;          // 0..15
                    float2 as = fmul2(w[p], SP);          // a * s
                    float2 lo = ffma2(w[p + 16], SP, as); // (a+b)*s
                    float2 hi = ffma2(w[p + 16], SM, as); // (a-b)*s
                    // lo -> element pair of jj-group, hi -> jj+8 group
                    if (half == 0) {
                        float2 as2 = fmul2(w[p + 1], SP);
                        float2 lo2 = ffma2(w[p + 17], SP, as2);
                        float2 hi2 = ffma2(w[p + 17], SM, as2);
                        float4 o1, o2;
                        o1.x = lo.x;  o1.y = lo.y;  o1.z = lo2.x; o1.w = lo2.y;
                        o2.x = hi.x;  o2.y = hi.y;  o2.z = hi2.x; o2.w = hi2.y;
                        y4[jj * 64 + t]       = o1;
                        y4[(jj + 8) * 64 + t] = o2;
                        break;   // both halves consumed
                    }
                }
            }
        }
        // No trailing barrier: buffers are single-use within the CTA.
    }
}

extern "C" void kernel_launch(void* const* d_in, const int* in_sizes, int n_in,
                              void* d_out, int out_size) {
    const float* x = (const float*)d_in[0];
    float* y = (float*)d_out;
    int total = in_sizes[0];
    int nrows = total / ROW;                      // 8192
    if (nrows % RPC == 0) {
        fwht4096_kernel<RPC><<<nrows / RPC, TPR>>>(x, y);
    } else {
        fwht4096_kernel<1><<<nrows, TPR>>>(x, y);
    }
}